// round 8
// baseline (speedup 1.0000x reference)
#include <cuda_runtime.h>
#include <cuda_bf16.h>

// ArcFaceLoss: N=8192 rows, C=32000 classes, fp32 pred, int target.
// loss_i = lse(logits_i) - S*margin(c_t)   where logits = 30*clamp(pred,-1,1),
// with the target column replaced by the arcface margin value.
//
// Single-kernel design (removes two ~2-4us tiny-kernel launches measured in
// R1/R5 profiles):
//  - clamp bounds logits to [-30,30] -> fixed softmax max of 30 -> one
//    streaming pass computes sum(exp(30c-30)); target column patched as a
//    rank-1 correction (one extra scalar load, L2-hit).
//  - dtype sniff (int64 vs int32 targets) done per-block at entry (64
//    high-word loads, L2-hit after wave 1) -> no separate launch.
//  - final mean via last-block pattern (threadfence + atomic counter),
//    deterministic fixed-order summation; counter self-resets for graph replay.

#define N_ROWS 8192
#define C_COLS 32000

__device__ float g_row_loss[N_ROWS];
__device__ unsigned int g_done = 0;

// M = 0.5
#define COS_M      0.877582561890373f
#define SIN_M      0.479425538604203f
#define MM_CONST   0.239712769302101f     // sin(0.5)*0.5
#define THRESH    -0.877582561890373f     // -cos(0.5)
#define S_SCALE    30.0f
#define K2         43.28085122666891f     // 30*log2(e)

__device__ __forceinline__ float clamp1(float x) {
    return fminf(fmaxf(x, -1.0f), 1.0f);
}

__device__ __forceinline__ float eterm(float c) {
    // exp(30*c - 30) == exp2(K2*c - K2)
    return exp2f(fmaf(K2, c, -K2));
}

__global__ __launch_bounds__(256) void arcface_kernel(
    const float* __restrict__ pred,
    const void*  __restrict__ tgt,
    float* __restrict__ out)
{
    const int row = blockIdx.x;
    const int tid = threadIdx.x;

    // ---- per-block dtype sniff (threads 0..63) ----------------------------
    // int64 targets (< 32000) have all-zero high words; 64 random int32
    // targets all being zero has prob ~(1/32000)^64. Reads are in-bounds for
    // both interpretations (int indices 1..127 < 8192).
    __shared__ unsigned sniff[2];
    __shared__ float warp_part[8];
    __shared__ bool is_last;
    if (tid == 0) is_last = false;
    if (tid < 64) {
        int hi = reinterpret_cast<const int*>(tgt)[2 * tid + 1];
        unsigned nz = __ballot_sync(0xFFFFFFFFu, hi != 0);
        if ((tid & 31) == 0) sniff[tid >> 5] = nz;
    }

    // ---- streaming sum(exp(30*clamp(x)-30)) over this row -----------------
    const float4* __restrict__ p =
        reinterpret_cast<const float4*>(pred + (size_t)row * C_COLS);

    float s0 = 0.0f, s1 = 0.0f;
    #pragma unroll 4
    for (int i = tid; i < C_COLS / 4; i += 256) {
        float4 v = __ldcs(&p[i]);
        s0 += eterm(clamp1(v.x)) + eterm(clamp1(v.y));
        s1 += eterm(clamp1(v.z)) + eterm(clamp1(v.w));
    }
    float s = s0 + s1;

    #pragma unroll
    for (int off = 16; off > 0; off >>= 1)
        s += __shfl_down_sync(0xFFFFFFFFu, s, off);
    if ((tid & 31) == 0) warp_part[tid >> 5] = s;
    __syncthreads();

    if (tid == 0) {
        float total = 0.0f;
        #pragma unroll
        for (int w = 0; w < 8; w++) total += warp_part[w];

        // target index (dtype-robust)
        long long t;
        if ((sniff[0] | sniff[1]) == 0u)
            t = reinterpret_cast<const long long*>(tgt)[row];
        else
            t = reinterpret_cast<const int*>(tgt)[row];

        float c = clamp1(pred[(size_t)row * C_COLS + t]);

        // arcface margin on the target cosine
        float tm;
        if (c > THRESH) {
            float sn = sqrtf(fmaxf(1.0f - c * c, 0.0f));
            tm = fmaf(c, COS_M, -sn * SIN_M);   // cos(acos(c)+M)
        } else {
            tm = c - MM_CONST;
        }

        // rank-1 correction: swap original target term for margin term
        float sum = total - eterm(c) + eterm(tm);

        // loss = lse - S*tm = (S + log(sum)) - S*tm
        g_row_loss[row] = S_SCALE + logf(sum) - S_SCALE * tm;
    }

    // ---- last-block final mean --------------------------------------------
    __threadfence();                       // publish g_row_loss[row]
    __syncthreads();                       // is_last init + row_loss write done
    if (tid == 0) {
        unsigned prev = atomicAdd(&g_done, 1u);
        is_last = (prev == (unsigned)(gridDim.x - 1));
    }
    __syncthreads();

    if (is_last) {
        // deterministic fixed-order reduction of all 8192 row losses
        float acc = 0.0f;
        #pragma unroll
        for (int i = tid; i < N_ROWS; i += 256) acc += g_row_loss[i];

        #pragma unroll
        for (int off = 16; off > 0; off >>= 1)
            acc += __shfl_down_sync(0xFFFFFFFFu, acc, off);
        if ((tid & 31) == 0) warp_part[tid >> 5] = acc;
        __syncthreads();

        if (tid == 0) {
            float v = 0.0f;
            #pragma unroll
            for (int w = 0; w < 8; w++) v += warp_part[w];
            out[0] = v * (1.0f / (float)N_ROWS);
            g_done = 0;                    // reset for next graph replay
        }
    }
}

extern "C" void kernel_launch(void* const* d_in, const int* in_sizes, int n_in,
                              void* d_out, int out_size)
{
    const float* pred = (const float*)d_in[0];
    const void*  tgt  = d_in[1];
    float* out = (float*)d_out;

    arcface_kernel<<<N_ROWS, 256>>>(pred, tgt, out);
}